// round 5
// baseline (speedup 1.0000x reference)
#include <cuda_runtime.h>
#include <cuda_bf16.h>
#include <math.h>
#include <stdint.h>

#define QN 4
#define DD 768
#define NN 1024
#define HH 512
#define MM 8192
#define DD2 1536

// ---------------- device scratch (no runtime allocation) -------------------
__device__ float g_res[MM*DD];
__device__ __align__(128) __nv_bfloat16 g_Ahi[MM*DD];
__device__ __align__(128) __nv_bfloat16 g_Alo[MM*DD];
__device__ __align__(128) __nv_bfloat16 g_Hhi[MM*DD2];
__device__ __align__(128) __nv_bfloat16 g_Hlo[MM*DD2];
#define WT_TOTAL 6029312
__device__ __align__(128) __nv_bfloat16 g_Wthi[WT_TOTAL];
__device__ __align__(128) __nv_bfloat16 g_Wtlo[WT_TOTAL];

// ---------------- PTX helpers ----------------------------------------------
__device__ __forceinline__ uint32_t smem_u32(const void* p) {
    uint32_t a;
    asm("{ .reg .u64 t; cvta.to.shared.u64 t, %1; cvt.u32.u64 %0, t; }" : "=r"(a) : "l"(p));
    return a;
}
#define CP_ASYNC16(dst, src) \
    asm volatile("cp.async.cg.shared.global [%0], [%1], 16;\n" :: "r"(dst), "l"(src))
#define CP_COMMIT() asm volatile("cp.async.commit_group;\n" ::: "memory")
#define CP_WAIT(n)  asm volatile("cp.async.wait_group %0;\n" :: "n"(n) : "memory")

#define LDSM4(f, addr) \
    asm volatile("ldmatrix.sync.aligned.m8n8.x4.shared.b16 {%0,%1,%2,%3}, [%4];\n" \
        : "=r"((f)[0]), "=r"((f)[1]), "=r"((f)[2]), "=r"((f)[3]) : "r"(addr))

#define MMA16816(d, a, b0, b1) \
    asm volatile("mma.sync.aligned.m16n8k16.row.col.f32.bf16.bf16.f32 " \
        "{%0,%1,%2,%3}, {%4,%5,%6,%7}, {%8,%9}, {%0,%1,%2,%3};\n" \
        : "+f"((d)[0]), "+f"((d)[1]), "+f"((d)[2]), "+f"((d)[3]) \
        : "r"((a)[0]), "r"((a)[1]), "r"((a)[2]), "r"((a)[3]), "r"(b0), "r"(b1))

// ---------------- small kernels --------------------------------------------
// init: res=x, split(x) -> Ahi/Alo
__global__ void init_kernel(const float* __restrict__ x) {
    int i = blockIdx.x * blockDim.x + threadIdx.x;
    if (i >= MM*DD/4) return;
    float4 a = ((const float4*)x)[i];
    ((float4*)g_res)[i] = a;
    float av[4] = {a.x, a.y, a.z, a.w};
    __nv_bfloat16 h[4], l[4];
#pragma unroll
    for (int j = 0; j < 4; j++) {
        h[j] = __float2bfloat16(av[j]);
        l[j] = __float2bfloat16(av[j] - __bfloat162float(h[j]));
    }
    ((ushort4*)g_Ahi)[i] = make_ushort4(*(unsigned short*)&h[0], *(unsigned short*)&h[1],
                                        *(unsigned short*)&h[2], *(unsigned short*)&h[3]);
    ((ushort4*)g_Alo)[i] = make_ushort4(*(unsigned short*)&l[0], *(unsigned short*)&l[1],
                                        *(unsigned short*)&l[2], *(unsigned short*)&l[3]);
}

// W[K,N] fp32 -> Wt_hi/lo[N,K] bf16 (tiled transpose + split)
__global__ void wsplit(const float* __restrict__ W, __nv_bfloat16* __restrict__ Thi,
                       __nv_bfloat16* __restrict__ Tlo, int K, int N) {
    __shared__ float t[32][33];
    int k0 = blockIdx.y * 32, n0 = blockIdx.x * 32;
    for (int i = threadIdx.y; i < 32; i += 8)
        t[i][threadIdx.x] = W[(size_t)(k0 + i) * N + n0 + threadIdx.x];
    __syncthreads();
    for (int i = threadIdx.y; i < 32; i += 8) {
        float val = t[threadIdx.x][i];
        __nv_bfloat16 h = __float2bfloat16(val);
        size_t o = (size_t)(n0 + i) * K + k0 + threadIdx.x;
        Thi[o] = h;
        Tlo[o] = __float2bfloat16(val - __bfloat162float(h));
    }
}

// ---------------- mma.sync split-bf16 GEMM, BK=32, 2 CTAs/SM ----------------
// C[M,Nc] = relu(bn(A @ W)). Row layout per 128B smem row: [hi 64B | lo 64B],
// 8x16B chunks, swizzle chunk ^= (row & 7). 3-stage cp.async, one sync/chunk.
// 128x128 CTA tile, 256 threads (8 warps x 64x32), hh + h*lo + lo*h -> fp32 acc.
// mode 0: fp32 out to Cf. mode 1: bf16 hi/lo split out to Chi/Clo.
#define GS_STAGE 32768            /* 16KB A + 16KB B per stage */
#define GS_SC    98304
#define SMEM_G   (98304 + 1024)

__global__ __launch_bounds__(256, 2)
void mma_gemm(const __nv_bfloat16* __restrict__ Ahi, const __nv_bfloat16* __restrict__ Alo,
              const __nv_bfloat16* __restrict__ Whi, const __nv_bfloat16* __restrict__ Wlo,
              const float* __restrict__ bb, const float* __restrict__ gg,
              const float* __restrict__ be, const float* __restrict__ mm_,
              const float* __restrict__ vv,
              float* __restrict__ Cf, __nv_bfloat16* __restrict__ Chi,
              __nv_bfloat16* __restrict__ Clo, int K, int mode)
{
    extern __shared__ __align__(1024) char smem[];
    const uint32_t sbase = smem_u32(smem);
    float* scp = (float*)(smem + GS_SC);
    float* ofp = scp + 128;
    const int tid = threadIdx.x;
    const int Nc = gridDim.x * 128;
    const int n0 = blockIdx.x * 128;
    const int m0 = blockIdx.y * 128;

    if (tid < 128) {
        int c = n0 + tid;
        float s = gg[c] * rsqrtf(vv[c] + 1e-5f);
        scp[tid] = s;
        ofp[tid] = (bb[c] - mm_[c]) * s + be[c];
    }

    const int lane = tid & 31, wid = tid >> 5;
    const int wm = (wid >> 2) << 6;     // 0 or 64
    const int wn = (wid & 3) << 5;      // 0,32,64,96

    float acc[4][4][4];
#pragma unroll
    for (int im = 0; im < 4; im++)
#pragma unroll
        for (int in = 0; in < 4; in++)
#pragma unroll
            for (int r = 0; r < 4; r++) acc[im][in][r] = 0.f;

    // ldmatrix address precompute (row stride 128B)
    uint32_t aoff[4]; int asw[4];
#pragma unroll
    for (int im = 0; im < 4; im++) {
        int r = wm + (im << 4) + (lane & 15);
        aoff[im] = (uint32_t)(r << 7);
        asw[im] = r & 7;
    }
    const int acb = lane >> 4;
    uint32_t boff[2]; int bsw[2];
#pragma unroll
    for (int jn = 0; jn < 2; jn++) {
        int r = wn + (jn << 4) + (lane & 7) + (((lane >> 4) & 1) << 3);
        boff[jn] = (uint32_t)(r << 7);
        bsw[jn] = r & 7;
    }
    const int bcb = (lane >> 3) & 1;

    const int NC = K >> 5;              // BK = 32

    // loader: 2 threads per row; tid&1 selects hi/lo half (4 chunks of 16B)
    const int lrow = tid >> 1;
    const int lhalf = tid & 1;
    const __nv_bfloat16* Asrc = lhalf ? Alo : Ahi;
    const __nv_bfloat16* Wsrc = lhalf ? Wlo : Whi;

    auto load_chunk = [&](int c, int s) {
        int k0 = c << 5;
        uint32_t bA = sbase + s * GS_STAGE;
        uint32_t bB = bA + 16384;
        const __nv_bfloat16* ag = Asrc + (size_t)(m0 + lrow) * K + k0;
        const __nv_bfloat16* wg = Wsrc + (size_t)(n0 + lrow) * K + k0;
        uint32_t rb = (uint32_t)(lrow << 7);
#pragma unroll
        for (int cn = 0; cn < 4; cn++) {
            int chunk = (lhalf << 2) + cn;
            uint32_t sw = rb + (uint32_t)((chunk ^ (lrow & 7)) << 4);
            CP_ASYNC16(bA + sw, ag + (cn << 3));
            CP_ASYNC16(bB + sw, wg + (cn << 3));
        }
    };

    load_chunk(0, 0); CP_COMMIT();
    load_chunk(1, 1); CP_COMMIT();

    int s = 0;                           // stage of chunk c
    for (int c = 0; c < NC; c++) {
        CP_WAIT(1);
        __syncthreads();
        if (c + 2 < NC) load_chunk(c + 2, (s + 2) % 3);
        CP_COMMIT();

        uint32_t sA = sbase + s * GS_STAGE;
        uint32_t sB = sA + 16384;
#pragma unroll
        for (int kk = 0; kk < 2; kk++) {
            const int ca = (kk << 1) + acb;
            const int cbk = (kk << 1) + bcb;
            uint32_t afh[4][4], bfh[2][4];
#pragma unroll
            for (int im = 0; im < 4; im++)
                LDSM4(afh[im], sA + aoff[im] + (uint32_t)((ca ^ asw[im]) << 4));
#pragma unroll
            for (int jn = 0; jn < 2; jn++)
                LDSM4(bfh[jn], sB + boff[jn] + (uint32_t)((cbk ^ bsw[jn]) << 4));
            // hh
#pragma unroll
            for (int im = 0; im < 4; im++)
#pragma unroll
                for (int in = 0; in < 4; in++) {
                    const uint32_t* bp = bfh[in >> 1];
                    if (in & 1) MMA16816(acc[im][in], afh[im], bp[2], bp[3]);
                    else        MMA16816(acc[im][in], afh[im], bp[0], bp[1]);
                }
            // hi * lo
            uint32_t bfl[2][4];
#pragma unroll
            for (int jn = 0; jn < 2; jn++)
                LDSM4(bfl[jn], sB + boff[jn] + (uint32_t)(((4 + cbk) ^ bsw[jn]) << 4));
#pragma unroll
            for (int im = 0; im < 4; im++)
#pragma unroll
                for (int in = 0; in < 4; in++) {
                    const uint32_t* bp = bfl[in >> 1];
                    if (in & 1) MMA16816(acc[im][in], afh[im], bp[2], bp[3]);
                    else        MMA16816(acc[im][in], afh[im], bp[0], bp[1]);
                }
            // lo * hi
            uint32_t afl[4][4];
#pragma unroll
            for (int im = 0; im < 4; im++)
                LDSM4(afl[im], sA + aoff[im] + (uint32_t)(((4 + ca) ^ asw[im]) << 4));
#pragma unroll
            for (int im = 0; im < 4; im++)
#pragma unroll
                for (int in = 0; in < 4; in++) {
                    const uint32_t* bp = bfh[in >> 1];
                    if (in & 1) MMA16816(acc[im][in], afl[im], bp[2], bp[3]);
                    else        MMA16816(acc[im][in], afl[im], bp[0], bp[1]);
                }
        }
        s = (s + 1) % 3;
    }

    // ---- epilogue: BN + ReLU ------------------------------------------------
    const int rbase = m0 + wm + (lane >> 2);
    const int clbase = wn + ((lane & 3) << 1);
#pragma unroll
    for (int im = 0; im < 4; im++) {
#pragma unroll
        for (int in = 0; in < 4; in++) {
            int row = rbase + (im << 4);
            int cl = clbase + (in << 3);
            float s0 = scp[cl], s1 = scp[cl + 1];
            float o0 = ofp[cl], o1 = ofp[cl + 1];
            float v0 = fmaxf(acc[im][in][0] * s0 + o0, 0.f);
            float v1 = fmaxf(acc[im][in][1] * s1 + o1, 0.f);
            float v2 = fmaxf(acc[im][in][2] * s0 + o0, 0.f);
            float v3 = fmaxf(acc[im][in][3] * s1 + o1, 0.f);
            size_t p0 = (size_t)row * Nc + n0 + cl;
            size_t p1 = (size_t)(row + 8) * Nc + n0 + cl;
            if (mode == 0) {
                float2 w0; w0.x = v0; w0.y = v1;
                float2 w1; w1.x = v2; w1.y = v3;
                *(float2*)&Cf[p0] = w0;
                *(float2*)&Cf[p1] = w1;
            } else {
                __nv_bfloat16 h0 = __float2bfloat16(v0);
                __nv_bfloat16 h1 = __float2bfloat16(v1);
                __nv_bfloat16 h2 = __float2bfloat16(v2);
                __nv_bfloat16 h3 = __float2bfloat16(v3);
                __nv_bfloat162 hp0; hp0.x = h0; hp0.y = h1;
                __nv_bfloat162 hp1; hp1.x = h2; hp1.y = h3;
                __nv_bfloat162 lp0, lp1;
                lp0.x = __float2bfloat16(v0 - __bfloat162float(h0));
                lp0.y = __float2bfloat16(v1 - __bfloat162float(h1));
                lp1.x = __float2bfloat16(v2 - __bfloat162float(h2));
                lp1.y = __float2bfloat16(v3 - __bfloat162float(h3));
                *(__nv_bfloat162*)&Chi[p0] = hp0;
                *(__nv_bfloat162*)&Chi[p1] = hp1;
                *(__nv_bfloat162*)&Clo[p0] = lp0;
                *(__nv_bfloat162*)&Clo[p1] = lp1;
            }
        }
    }
}

// ---------------- token kernel ----------------------------------------------
// split_mode 0: res -= cb[idx]; emit split(res) -> g_Ahi/g_Alo
// split_mode 1: r = res - cb[idx] (no writeback); emit split(x - r) (= qout)
__global__ void token_kernel(const float* __restrict__ z,
                             const float* __restrict__ gum,
                             const float* __restrict__ cb,
                             const float* __restrict__ x,
                             float* __restrict__ ent_out,
                             float* __restrict__ lat_out,
                             float* __restrict__ idx_out,
                             int split_mode)
{
    const int t = blockIdx.x;
    const int tid = threadIdx.x;
    const int lane = tid & 31, wrp = tid >> 5;
    const float* zr = z + (size_t)t * NN;
    const float* gr = gum + (size_t)t * NN;

    __shared__ float swa[8];
    __shared__ float swb[8];
    __shared__ int   swi[8];

    float zv[4];
    float lmax = -INFINITY;
    float amax = -INFINITY;
    int   aidx = 0x7fffffff;
#pragma unroll
    for (int j = 0; j < 4; j++) {
        int c = tid + 256 * j;
        float zz = zr[c];
        zv[j] = zz;
        lmax = fmaxf(lmax, zz);
        float lg = zz + gr[c];
        if (lg > amax) { amax = lg; aidx = c; }
    }
#pragma unroll
    for (int o = 16; o > 0; o >>= 1) {
        lmax = fmaxf(lmax, __shfl_xor_sync(0xffffffffu, lmax, o));
        float ov = __shfl_xor_sync(0xffffffffu, amax, o);
        int   oi = __shfl_xor_sync(0xffffffffu, aidx, o);
        if (ov > amax || (ov == amax && oi < aidx)) { amax = ov; aidx = oi; }
    }
    if (lane == 0) { swa[wrp] = lmax; swb[wrp] = amax; swi[wrp] = aidx; }
    __syncthreads();
    float zmax = swa[0];
    float bv = swb[0]; int bi = swi[0];
#pragma unroll
    for (int w = 1; w < 8; w++) {
        zmax = fmaxf(zmax, swa[w]);
        float ov = swb[w]; int oi = swi[w];
        if (ov > bv || (ov == bv && oi < bi)) { bv = ov; bi = oi; }
    }
    const int idx = bi;
    __syncthreads();

    float se = 0.f;
#pragma unroll
    for (int j = 0; j < 4; j++) se += expf(zv[j] - zmax);
#pragma unroll
    for (int o = 16; o > 0; o >>= 1) se += __shfl_xor_sync(0xffffffffu, se, o);
    if (lane == 0) swa[wrp] = se;
    __syncthreads();
    float tot = 0.f;
#pragma unroll
    for (int w = 0; w < 8; w++) tot += swa[w];
    const float inv = 1.f / tot;

    float entp = 0.f;
#pragma unroll
    for (int j = 0; j < 4; j++) {
        int c = tid + 256 * j;
        float qy = expf(zv[j] - zmax) * inv;
        entp -= qy * logf(qy + 1e-10f);
        lat_out[(size_t)t * NN + c] = qy * logf(qy * 1024.f + 1e-10f);
    }
#pragma unroll
    for (int o = 16; o > 0; o >>= 1) entp += __shfl_xor_sync(0xffffffffu, entp, o);
    __syncthreads();
    if (lane == 0) swb[wrp] = entp;
    __syncthreads();
    if (tid == 0) {
        float e = 0.f;
#pragma unroll
        for (int w = 0; w < 8; w++) e += swb[w];
        ent_out[t] = e;
        idx_out[t] = (float)idx;
    }

    const float* cbr = cb + (size_t)idx * DD;
    float* rr = g_res + (size_t)t * DD;
    const float* xr = x + (size_t)t * DD;
    __nv_bfloat16* oh = g_Ahi + (size_t)t * DD;
    __nv_bfloat16* ol = g_Alo + (size_t)t * DD;
#pragma unroll
    for (int j = 0; j < 3; j++) {
        int d = tid + 256 * j;
        float r = rr[d] - cbr[d];
        float sv;
        if (split_mode) {
            sv = xr[d] - r;              // qout = x - res_final
        } else {
            rr[d] = r;
            sv = r;
        }
        __nv_bfloat16 h = __float2bfloat16(sv);
        oh[d] = h;
        ol[d] = __float2bfloat16(sv - __bfloat162float(h));
    }
}

// ---------------- host launch ----------------------------------------------
extern "C" void kernel_launch(void* const* d_in, const int* in_sizes, int n_in,
                              void* d_out, int out_size)
{
    const float* x    = (const float*)d_in[0];
    const float* cb   = (const float*)d_in[1];
    const float* pW1  = (const float*)d_in[2];
    const float* pb1  = (const float*)d_in[3];
    const float* pg1  = (const float*)d_in[4];
    const float* pbe1 = (const float*)d_in[5];
    const float* pm1  = (const float*)d_in[6];
    const float* pv1  = (const float*)d_in[7];
    const float* pW2  = (const float*)d_in[8];
    const float* pb2  = (const float*)d_in[9];
    const float* pg2  = (const float*)d_in[10];
    const float* pbe2 = (const float*)d_in[11];
    const float* pm2  = (const float*)d_in[12];
    const float* pv2  = (const float*)d_in[13];
    const float* dW1  = (const float*)d_in[14];
    const float* db1  = (const float*)d_in[15];
    const float* dg1  = (const float*)d_in[16];
    const float* dbe1 = (const float*)d_in[17];
    const float* dm1  = (const float*)d_in[18];
    const float* dv1  = (const float*)d_in[19];
    const float* dW2  = (const float*)d_in[20];
    const float* db2  = (const float*)d_in[21];
    const float* dg2  = (const float*)d_in[22];
    const float* dbe2 = (const float*)d_in[23];
    const float* dm2  = (const float*)d_in[24];
    const float* dv2  = (const float*)d_in[25];
    const float* gum  = (const float*)d_in[26];

    float* out  = (float*)d_out;
    float* xhat = out;                                  // [MM, DD]
    float* ent  = xhat + (size_t)MM * DD;               // [QN, MM]
    float* lat  = ent  + (size_t)QN * MM;               // [QN, MM, NN]
    float* idxo = lat  + (size_t)QN * MM * NN;          // [QN, MM]
    float* zs   = idxo + (size_t)QN * MM;               // [QN, MM, NN]

    __nv_bfloat16 *Ahi, *Alo, *Hhi, *Hlo, *Wthi, *Wtlo;
    cudaGetSymbolAddress((void**)&Ahi,  g_Ahi);
    cudaGetSymbolAddress((void**)&Alo,  g_Alo);
    cudaGetSymbolAddress((void**)&Hhi,  g_Hhi);
    cudaGetSymbolAddress((void**)&Hlo,  g_Hlo);
    cudaGetSymbolAddress((void**)&Wthi, g_Wthi);
    cudaGetSymbolAddress((void**)&Wtlo, g_Wtlo);

    cudaFuncSetAttribute(mma_gemm, cudaFuncAttributeMaxDynamicSharedMemorySize, SMEM_G);

    const size_t O_P1 = 0;
    const size_t SZ_P1 = (size_t)HH * DD;
    const size_t O_P2 = 4 * SZ_P1;
    const size_t SZ_P2 = (size_t)NN * HH;
    const size_t O_D1 = O_P2 + 4 * SZ_P2;
    const size_t SZ_D1 = (size_t)DD2 * DD;
    const size_t O_D2 = O_D1 + SZ_D1;

    init_kernel<<<(MM*DD/4 + 255) / 256, 256>>>(x);

    dim3 wtb(32, 8);
    for (int i = 0; i < QN; i++) {
        wsplit<<<dim3(HH/32, DD/32), wtb>>>(pW1 + (size_t)i*DD*HH,
                                            Wthi + O_P1 + i*SZ_P1, Wtlo + O_P1 + i*SZ_P1, DD, HH);
        wsplit<<<dim3(NN/32, HH/32), wtb>>>(pW2 + (size_t)i*HH*NN,
                                            Wthi + O_P2 + i*SZ_P2, Wtlo + O_P2 + i*SZ_P2, HH, NN);
    }
    wsplit<<<dim3(DD2/32, DD/32), wtb>>>(dW1, Wthi + O_D1, Wtlo + O_D1, DD, DD2);
    wsplit<<<dim3(DD/32, DD2/32), wtb>>>(dW2, Wthi + O_D2, Wtlo + O_D2, DD2, DD);

    for (int i = 0; i < QN; i++) {
        // h = blk(res @ pW1) -> bf16 split [8192 x 512]
        mma_gemm<<<dim3(HH/128, MM/128), 256, SMEM_G>>>(
            Ahi, Alo, Wthi + O_P1 + i*SZ_P1, Wtlo + O_P1 + i*SZ_P1,
            pb1 + i*HH, pg1 + i*HH, pbe1 + i*HH, pm1 + i*HH, pv1 + i*HH,
            nullptr, Hhi, Hlo, DD, 1);
        // z = blk(h @ pW2) -> fp32 zs slice [8192 x 1024]
        float* z_i = zs + (size_t)i * MM * NN;
        mma_gemm<<<dim3(NN/128, MM/128), 256, SMEM_G>>>(
            Hhi, Hlo, Wthi + O_P2 + i*SZ_P2, Wtlo + O_P2 + i*SZ_P2,
            pb2 + i*NN, pg2 + i*NN, pbe2 + i*NN, pm2 + i*NN, pv2 + i*NN,
            z_i, nullptr, nullptr, HH, 0);
        token_kernel<<<MM, 256>>>(
            z_i, gum + (size_t)i * MM * NN, cb + (size_t)i * NN * DD, x,
            ent + (size_t)i * MM, lat + (size_t)i * MM * NN, idxo + (size_t)i * MM,
            (i == QN - 1) ? 1 : 0);
    }

    // decoder (Ahi/Alo hold split(qout))
    mma_gemm<<<dim3(DD2/128, MM/128), 256, SMEM_G>>>(
        Ahi, Alo, Wthi + O_D1, Wtlo + O_D1,
        db1, dg1, dbe1, dm1, dv1,
        nullptr, Hhi, Hlo, DD, 1);
    mma_gemm<<<dim3(DD/128, MM/128), 256, SMEM_G>>>(
        Hhi, Hlo, Wthi + O_D2, Wtlo + O_D2,
        db2, dg2, dbe2, dm2, dv2,
        xhat, nullptr, nullptr, DD2, 0);
}

// round 7
// speedup vs baseline: 1.5578x; 1.5578x over previous
#include <cuda_runtime.h>
#include <cuda_bf16.h>
#include <math.h>
#include <stdint.h>

#define QN 4
#define DD 768
#define NN 1024
#define HH 512
#define MM 8192
#define DD2 1536

// ---------------- device scratch (no runtime allocation) -------------------
__device__ float g_res[MM*DD];
__device__ __align__(128) __nv_bfloat16 g_Ahi[MM*DD];
__device__ __align__(128) __nv_bfloat16 g_Alo[MM*DD];
__device__ __align__(128) __nv_bfloat16 g_Hhi[MM*DD2];
__device__ __align__(128) __nv_bfloat16 g_Hlo[MM*DD2];
#define WT_TOTAL 6029312
__device__ __align__(128) __nv_bfloat16 g_Wthi[WT_TOTAL];
__device__ __align__(128) __nv_bfloat16 g_Wtlo[WT_TOTAL];

// ---------------- PTX helpers ----------------------------------------------
__device__ __forceinline__ uint32_t smem_u32(const void* p) {
    uint32_t a;
    asm("{ .reg .u64 t; cvta.to.shared.u64 t, %1; cvt.u32.u64 %0, t; }" : "=r"(a) : "l"(p));
    return a;
}
#define CP_ASYNC16(dst, src) \
    asm volatile("cp.async.cg.shared.global [%0], [%1], 16;\n" :: "r"(dst), "l"(src))
#define CP_COMMIT() asm volatile("cp.async.commit_group;\n" ::: "memory")
#define CP_WAIT(n)  asm volatile("cp.async.wait_group %0;\n" :: "n"(n) : "memory")

#define LDSM4(f, addr) \
    asm volatile("ldmatrix.sync.aligned.m8n8.x4.shared.b16 {%0,%1,%2,%3}, [%4];\n" \
        : "=r"((f)[0]), "=r"((f)[1]), "=r"((f)[2]), "=r"((f)[3]) : "r"(addr))

#define MMA16816(d, a, b0, b1) \
    asm volatile("mma.sync.aligned.m16n8k16.row.col.f32.bf16.bf16.f32 " \
        "{%0,%1,%2,%3}, {%4,%5,%6,%7}, {%8,%9}, {%0,%1,%2,%3};\n" \
        : "+f"((d)[0]), "+f"((d)[1]), "+f"((d)[2]), "+f"((d)[3]) \
        : "r"((a)[0]), "r"((a)[1]), "r"((a)[2]), "r"((a)[3]), "r"(b0), "r"(b1))

// ---------------- small kernels --------------------------------------------
// init: res=x, split(x) -> Ahi/Alo
__global__ void init_kernel(const float* __restrict__ x) {
    int i = blockIdx.x * blockDim.x + threadIdx.x;
    if (i >= MM*DD/4) return;
    float4 a = ((const float4*)x)[i];
    ((float4*)g_res)[i] = a;
    float av[4] = {a.x, a.y, a.z, a.w};
    __nv_bfloat16 h[4], l[4];
#pragma unroll
    for (int j = 0; j < 4; j++) {
        h[j] = __float2bfloat16(av[j]);
        l[j] = __float2bfloat16(av[j] - __bfloat162float(h[j]));
    }
    ((ushort4*)g_Ahi)[i] = make_ushort4(*(unsigned short*)&h[0], *(unsigned short*)&h[1],
                                        *(unsigned short*)&h[2], *(unsigned short*)&h[3]);
    ((ushort4*)g_Alo)[i] = make_ushort4(*(unsigned short*)&l[0], *(unsigned short*)&l[1],
                                        *(unsigned short*)&l[2], *(unsigned short*)&l[3]);
}

// W[K,N] fp32 -> Wt_hi/lo[N,K] bf16 (tiled transpose + split)
__global__ void wsplit(const float* __restrict__ W, __nv_bfloat16* __restrict__ Thi,
                       __nv_bfloat16* __restrict__ Tlo, int K, int N) {
    __shared__ float t[32][33];
    int k0 = blockIdx.y * 32, n0 = blockIdx.x * 32;
    for (int i = threadIdx.y; i < 32; i += 8)
        t[i][threadIdx.x] = W[(size_t)(k0 + i) * N + n0 + threadIdx.x];
    __syncthreads();
    for (int i = threadIdx.y; i < 32; i += 8) {
        float val = t[threadIdx.x][i];
        __nv_bfloat16 h = __float2bfloat16(val);
        size_t o = (size_t)(n0 + i) * K + k0 + threadIdx.x;
        Thi[o] = h;
        Tlo[o] = __float2bfloat16(val - __bfloat162float(h));
    }
}

// ---------------- mma.sync split-bf16 GEMM, interleaved hi/lo ---------------
// C[M,Nc] = relu(bn(A @ W)). Per K-chunk (BK=64) load Ahi|Alo and Whi|Wlo once
// (256B rows: [hi 128B | lo 128B], SW128 swizzle per 128B atom) and accumulate
// hh + h*lo + lo*h into the same fp32 acc. 128x128 CTA tile, 3-stage cp.async,
// ONE __syncthreads per chunk. 256 threads (8 warps x 64x32), 1 CTA/SM.
// mode 0: fp32 out to Cf. mode 1: bf16 hi/lo split out to Chi/Clo.
#define GS_STAGE 65536            /* 32KB A(hi|lo) + 32KB W(hi|lo) */
#define GS_SC    196608
#define SMEM_G   (196608 + 1024)

__global__ __launch_bounds__(256, 1)
void mma_gemm(const __nv_bfloat16* __restrict__ Ahi, const __nv_bfloat16* __restrict__ Alo,
              const __nv_bfloat16* __restrict__ Whi, const __nv_bfloat16* __restrict__ Wlo,
              const float* __restrict__ bb, const float* __restrict__ gg,
              const float* __restrict__ be, const float* __restrict__ mm_,
              const float* __restrict__ vv,
              float* __restrict__ Cf, __nv_bfloat16* __restrict__ Chi,
              __nv_bfloat16* __restrict__ Clo, int K, int mode)
{
    extern __shared__ __align__(1024) char smem[];
    const uint32_t sbase = smem_u32(smem);
    float* scp = (float*)(smem + GS_SC);
    float* ofp = scp + 128;
    const int tid = threadIdx.x;
    const int Nc = gridDim.x * 128;
    const int n0 = blockIdx.x * 128;
    const int m0 = blockIdx.y * 128;

    if (tid < 128) {
        int c = n0 + tid;
        float s = gg[c] * rsqrtf(vv[c] + 1e-5f);
        scp[tid] = s;
        ofp[tid] = (bb[c] - mm_[c]) * s + be[c];
    }

    const int lane = tid & 31, wid = tid >> 5;
    const int wm = (wid >> 2) << 6;     // 0 or 64
    const int wn = (wid & 3) << 5;      // 0,32,64,96

    float acc[4][4][4];
#pragma unroll
    for (int im = 0; im < 4; im++)
#pragma unroll
        for (int in = 0; in < 4; in++)
#pragma unroll
            for (int r = 0; r < 4; r++) acc[im][in][r] = 0.f;

    // ldmatrix address precompute (row stride 256B)
    uint32_t aoff[4]; int asw[4];
#pragma unroll
    for (int im = 0; im < 4; im++) {
        int r = wm + (im << 4) + (lane & 15);
        aoff[im] = (uint32_t)(r << 8);
        asw[im] = r & 7;
    }
    const int acb = lane >> 4;
    uint32_t boff[2]; int bsw[2];
#pragma unroll
    for (int jn = 0; jn < 2; jn++) {
        int r = wn + (jn << 4) + (lane & 7) + (((lane >> 4) & 1) << 3);
        boff[jn] = (uint32_t)(r << 8);
        bsw[jn] = r & 7;
    }
    const int bcb = (lane >> 3) & 1;

    const int NC = K >> 6;

    // loader: per thread, 16B chunk index constant (tid&15): half = hi/lo select
    const int lrow0 = tid >> 4;          // 0..15
    const int lc16  = tid & 15;
    const int lhalf = lc16 >> 3;         // 0=hi, 1=lo
    const int lcc   = lc16 & 7;
    const __nv_bfloat16* Asrc = lhalf ? Alo : Ahi;
    const __nv_bfloat16* Wsrc = lhalf ? Wlo : Whi;
    const uint32_t lhoff = (uint32_t)(lhalf << 7);

    auto load_chunk = [&](int c, int s) {
        int k0 = c << 6;
        uint32_t bA = sbase + s * GS_STAGE;
        uint32_t bB = bA + 32768;
#pragma unroll
        for (int j = 0; j < 8; j++) {
            int row = lrow0 + (j << 4);
            uint32_t sw = (uint32_t)(row << 8) + lhoff + (uint32_t)((lcc ^ (row & 7)) << 4);
            CP_ASYNC16(bA + sw, Asrc + (size_t)(m0 + row) * K + k0 + (lcc << 3));
            CP_ASYNC16(bB + sw, Wsrc + (size_t)(n0 + row) * K + k0 + (lcc << 3));
        }
    };

    load_chunk(0, 0); CP_COMMIT();
    load_chunk(1, 1); CP_COMMIT();

    for (int c = 0; c < NC; c++) {
        CP_WAIT(1);                         // chunk c's data arrived
        __syncthreads();                    // visible to all; stage (c-1)%3 free
        if (c + 2 < NC) load_chunk(c + 2, (c + 2) % 3);
        CP_COMMIT();

        uint32_t sA = sbase + (c % 3) * GS_STAGE;
        uint32_t sB = sA + 32768;
#pragma unroll
        for (int kk = 0; kk < 4; kk++) {
            uint32_t afh[4][4], afl[4][4], bfh[2][4], bfl[2][4];
            const int sela = (kk << 1) + acb;
            const int selb = (kk << 1) + bcb;
#pragma unroll
            for (int im = 0; im < 4; im++) {
                uint32_t base = sA + aoff[im] + (uint32_t)((sela ^ asw[im]) << 4);
                LDSM4(afh[im], base);
                LDSM4(afl[im], base + 128);
            }
#pragma unroll
            for (int jn = 0; jn < 2; jn++) {
                uint32_t base = sB + boff[jn] + (uint32_t)((selb ^ bsw[jn]) << 4);
                LDSM4(bfh[jn], base);
                LDSM4(bfl[jn], base + 128);
            }
            // hh
#pragma unroll
            for (int im = 0; im < 4; im++)
#pragma unroll
                for (int in = 0; in < 4; in++) {
                    const uint32_t* bp = bfh[in >> 1];
                    if (in & 1) MMA16816(acc[im][in], afh[im], bp[2], bp[3]);
                    else        MMA16816(acc[im][in], afh[im], bp[0], bp[1]);
                }
            // hi * lo
#pragma unroll
            for (int im = 0; im < 4; im++)
#pragma unroll
                for (int in = 0; in < 4; in++) {
                    const uint32_t* bp = bfl[in >> 1];
                    if (in & 1) MMA16816(acc[im][in], afh[im], bp[2], bp[3]);
                    else        MMA16816(acc[im][in], afh[im], bp[0], bp[1]);
                }
            // lo * hi
#pragma unroll
            for (int im = 0; im < 4; im++)
#pragma unroll
                for (int in = 0; in < 4; in++) {
                    const uint32_t* bp = bfh[in >> 1];
                    if (in & 1) MMA16816(acc[im][in], afl[im], bp[2], bp[3]);
                    else        MMA16816(acc[im][in], afl[im], bp[0], bp[1]);
                }
        }
    }

    // ---- epilogue: BN + ReLU ------------------------------------------------
    const int rbase = m0 + wm + (lane >> 2);
    const int clbase = wn + ((lane & 3) << 1);
#pragma unroll
    for (int im = 0; im < 4; im++) {
#pragma unroll
        for (int in = 0; in < 4; in++) {
            int row = rbase + (im << 4);
            int cl = clbase + (in << 3);
            float s0 = scp[cl], s1 = scp[cl + 1];
            float o0 = ofp[cl], o1 = ofp[cl + 1];
            float v0 = fmaxf(acc[im][in][0] * s0 + o0, 0.f);
            float v1 = fmaxf(acc[im][in][1] * s1 + o1, 0.f);
            float v2 = fmaxf(acc[im][in][2] * s0 + o0, 0.f);
            float v3 = fmaxf(acc[im][in][3] * s1 + o1, 0.f);
            size_t p0 = (size_t)row * Nc + n0 + cl;
            size_t p1 = (size_t)(row + 8) * Nc + n0 + cl;
            if (mode == 0) {
                float2 w0; w0.x = v0; w0.y = v1;
                float2 w1; w1.x = v2; w1.y = v3;
                *(float2*)&Cf[p0] = w0;
                *(float2*)&Cf[p1] = w1;
            } else {
                __nv_bfloat16 h0 = __float2bfloat16(v0);
                __nv_bfloat16 h1 = __float2bfloat16(v1);
                __nv_bfloat16 h2 = __float2bfloat16(v2);
                __nv_bfloat16 h3 = __float2bfloat16(v3);
                __nv_bfloat162 hp0; hp0.x = h0; hp0.y = h1;
                __nv_bfloat162 hp1; hp1.x = h2; hp1.y = h3;
                __nv_bfloat162 lp0, lp1;
                lp0.x = __float2bfloat16(v0 - __bfloat162float(h0));
                lp0.y = __float2bfloat16(v1 - __bfloat162float(h1));
                lp1.x = __float2bfloat16(v2 - __bfloat162float(h2));
                lp1.y = __float2bfloat16(v3 - __bfloat162float(h3));
                *(__nv_bfloat162*)&Chi[p0] = hp0;
                *(__nv_bfloat162*)&Chi[p1] = hp1;
                *(__nv_bfloat162*)&Clo[p0] = lp0;
                *(__nv_bfloat162*)&Clo[p1] = lp1;
            }
        }
    }
}

// ---------------- token kernel ----------------------------------------------
// split_mode 0: res -= cb[idx]; emit split(res) -> g_Ahi/g_Alo
// split_mode 1: r = res - cb[idx] (no writeback); emit split(x - r) (= qout)
__global__ void token_kernel(const float* __restrict__ z,
                             const float* __restrict__ gum,
                             const float* __restrict__ cb,
                             const float* __restrict__ x,
                             float* __restrict__ ent_out,
                             float* __restrict__ lat_out,
                             float* __restrict__ idx_out,
                             int split_mode)
{
    const int t = blockIdx.x;
    const int tid = threadIdx.x;
    const int lane = tid & 31, wrp = tid >> 5;
    const float* zr = z + (size_t)t * NN;
    const float* gr = gum + (size_t)t * NN;

    __shared__ float swa[8];
    __shared__ float swb[8];
    __shared__ int   swi[8];

    float zv[4];
    float lmax = -INFINITY;
    float amax = -INFINITY;
    int   aidx = 0x7fffffff;
#pragma unroll
    for (int j = 0; j < 4; j++) {
        int c = tid + 256 * j;
        float zz = zr[c];
        zv[j] = zz;
        lmax = fmaxf(lmax, zz);
        float lg = zz + gr[c];
        if (lg > amax) { amax = lg; aidx = c; }
    }
#pragma unroll
    for (int o = 16; o > 0; o >>= 1) {
        lmax = fmaxf(lmax, __shfl_xor_sync(0xffffffffu, lmax, o));
        float ov = __shfl_xor_sync(0xffffffffu, amax, o);
        int   oi = __shfl_xor_sync(0xffffffffu, aidx, o);
        if (ov > amax || (ov == amax && oi < aidx)) { amax = ov; aidx = oi; }
    }
    if (lane == 0) { swa[wrp] = lmax; swb[wrp] = amax; swi[wrp] = aidx; }
    __syncthreads();
    float zmax = swa[0];
    float bv = swb[0]; int bi = swi[0];
#pragma unroll
    for (int w = 1; w < 8; w++) {
        zmax = fmaxf(zmax, swa[w]);
        float ov = swb[w]; int oi = swi[w];
        if (ov > bv || (ov == bv && oi < bi)) { bv = ov; bi = oi; }
    }
    const int idx = bi;
    __syncthreads();

    float se = 0.f;
#pragma unroll
    for (int j = 0; j < 4; j++) se += expf(zv[j] - zmax);
#pragma unroll
    for (int o = 16; o > 0; o >>= 1) se += __shfl_xor_sync(0xffffffffu, se, o);
    if (lane == 0) swa[wrp] = se;
    __syncthreads();
    float tot = 0.f;
#pragma unroll
    for (int w = 0; w < 8; w++) tot += swa[w];
    const float inv = 1.f / tot;

    float entp = 0.f;
#pragma unroll
    for (int j = 0; j < 4; j++) {
        int c = tid + 256 * j;
        float qy = expf(zv[j] - zmax) * inv;
        entp -= qy * logf(qy + 1e-10f);
        lat_out[(size_t)t * NN + c] = qy * logf(qy * 1024.f + 1e-10f);
    }
#pragma unroll
    for (int o = 16; o > 0; o >>= 1) entp += __shfl_xor_sync(0xffffffffu, entp, o);
    __syncthreads();
    if (lane == 0) swb[wrp] = entp;
    __syncthreads();
    if (tid == 0) {
        float e = 0.f;
#pragma unroll
        for (int w = 0; w < 8; w++) e += swb[w];
        ent_out[t] = e;
        idx_out[t] = (float)idx;
    }

    const float* cbr = cb + (size_t)idx * DD;
    float* rr = g_res + (size_t)t * DD;
    const float* xr = x + (size_t)t * DD;
    __nv_bfloat16* oh = g_Ahi + (size_t)t * DD;
    __nv_bfloat16* ol = g_Alo + (size_t)t * DD;
#pragma unroll
    for (int j = 0; j < 3; j++) {
        int d = tid + 256 * j;
        float r = rr[d] - cbr[d];
        float sv;
        if (split_mode) {
            sv = xr[d] - r;              // qout = x - res_final
        } else {
            rr[d] = r;
            sv = r;
        }
        __nv_bfloat16 h = __float2bfloat16(sv);
        oh[d] = h;
        ol[d] = __float2bfloat16(sv - __bfloat162float(h));
    }
}

// ---------------- host launch ----------------------------------------------
extern "C" void kernel_launch(void* const* d_in, const int* in_sizes, int n_in,
                              void* d_out, int out_size)
{
    const float* x    = (const float*)d_in[0];
    const float* cb   = (const float*)d_in[1];
    const float* pW1  = (const float*)d_in[2];
    const float* pb1  = (const float*)d_in[3];
    const float* pg1  = (const float*)d_in[4];
    const float* pbe1 = (const float*)d_in[5];
    const float* pm1  = (const float*)d_in[6];
    const float* pv1  = (const float*)d_in[7];
    const float* pW2  = (const float*)d_in[8];
    const float* pb2  = (const float*)d_in[9];
    const float* pg2  = (const float*)d_in[10];
    const float* pbe2 = (const float*)d_in[11];
    const float* pm2  = (const float*)d_in[12];
    const float* pv2  = (const float*)d_in[13];
    const float* dW1  = (const float*)d_in[14];
    const float* db1  = (const float*)d_in[15];
    const float* dg1  = (const float*)d_in[16];
    const float* dbe1 = (const float*)d_in[17];
    const float* dm1  = (const float*)d_in[18];
    const float* dv1  = (const float*)d_in[19];
    const float* dW2  = (const float*)d_in[20];
    const float* db2  = (const float*)d_in[21];
    const float* dg2  = (const float*)d_in[22];
    const float* dbe2 = (const float*)d_in[23];
    const float* dm2  = (const float*)d_in[24];
    const float* dv2  = (const float*)d_in[25];
    const float* gum  = (const float*)d_in[26];

    float* out  = (float*)d_out;
    float* xhat = out;                                  // [MM, DD]
    float* ent  = xhat + (size_t)MM * DD;               // [QN, MM]
    float* lat  = ent  + (size_t)QN * MM;               // [QN, MM, NN]
    float* idxo = lat  + (size_t)QN * MM * NN;          // [QN, MM]
    float* zs   = idxo + (size_t)QN * MM;               // [QN, MM, NN]

    __nv_bfloat16 *Ahi, *Alo, *Hhi, *Hlo, *Wthi, *Wtlo;
    cudaGetSymbolAddress((void**)&Ahi,  g_Ahi);
    cudaGetSymbolAddress((void**)&Alo,  g_Alo);
    cudaGetSymbolAddress((void**)&Hhi,  g_Hhi);
    cudaGetSymbolAddress((void**)&Hlo,  g_Hlo);
    cudaGetSymbolAddress((void**)&Wthi, g_Wthi);
    cudaGetSymbolAddress((void**)&Wtlo, g_Wtlo);

    cudaFuncSetAttribute(mma_gemm, cudaFuncAttributeMaxDynamicSharedMemorySize, SMEM_G);

    const size_t O_P1 = 0;
    const size_t SZ_P1 = (size_t)HH * DD;
    const size_t O_P2 = 4 * SZ_P1;
    const size_t SZ_P2 = (size_t)NN * HH;
    const size_t O_D1 = O_P2 + 4 * SZ_P2;
    const size_t SZ_D1 = (size_t)DD2 * DD;
    const size_t O_D2 = O_D1 + SZ_D1;

    init_kernel<<<(MM*DD/4 + 255) / 256, 256>>>(x);

    dim3 wtb(32, 8);
    for (int i = 0; i < QN; i++) {
        wsplit<<<dim3(HH/32, DD/32), wtb>>>(pW1 + (size_t)i*DD*HH,
                                            Wthi + O_P1 + i*SZ_P1, Wtlo + O_P1 + i*SZ_P1, DD, HH);
        wsplit<<<dim3(NN/32, HH/32), wtb>>>(pW2 + (size_t)i*HH*NN,
                                            Wthi + O_P2 + i*SZ_P2, Wtlo + O_P2 + i*SZ_P2, HH, NN);
    }
    wsplit<<<dim3(DD2/32, DD/32), wtb>>>(dW1, Wthi + O_D1, Wtlo + O_D1, DD, DD2);
    wsplit<<<dim3(DD/32, DD2/32), wtb>>>(dW2, Wthi + O_D2, Wtlo + O_D2, DD2, DD);

    for (int i = 0; i < QN; i++) {
        // h = blk(res @ pW1) -> bf16 split [8192 x 512]
        mma_gemm<<<dim3(HH/128, MM/128), 256, SMEM_G>>>(
            Ahi, Alo, Wthi + O_P1 + i*SZ_P1, Wtlo + O_P1 + i*SZ_P1,
            pb1 + i*HH, pg1 + i*HH, pbe1 + i*HH, pm1 + i*HH, pv1 + i*HH,
            nullptr, Hhi, Hlo, DD, 1);
        // z = blk(h @ pW2) -> fp32 zs slice [8192 x 1024]
        float* z_i = zs + (size_t)i * MM * NN;
        mma_gemm<<<dim3(NN/128, MM/128), 256, SMEM_G>>>(
            Hhi, Hlo, Wthi + O_P2 + i*SZ_P2, Wtlo + O_P2 + i*SZ_P2,
            pb2 + i*NN, pg2 + i*NN, pbe2 + i*NN, pm2 + i*NN, pv2 + i*NN,
            z_i, nullptr, nullptr, HH, 0);
        token_kernel<<<MM, 256>>>(
            z_i, gum + (size_t)i * MM * NN, cb + (size_t)i * NN * DD, x,
            ent + (size_t)i * MM, lat + (size_t)i * MM * NN, idxo + (size_t)i * MM,
            (i == QN - 1) ? 1 : 0);
    }

    // decoder (Ahi/Alo hold split(qout))
    mma_gemm<<<dim3(DD2/128, MM/128), 256, SMEM_G>>>(
        Ahi, Alo, Wthi + O_D1, Wtlo + O_D1,
        db1, dg1, dbe1, dm1, dv1,
        nullptr, Hhi, Hlo, DD, 1);
    mma_gemm<<<dim3(DD/128, MM/128), 256, SMEM_G>>>(
        Hhi, Hlo, Wthi + O_D2, Wtlo + O_D2,
        db2, dg2, dbe2, dm2, dv2,
        xhat, nullptr, nullptr, DD2, 0);
}

// round 9
// speedup vs baseline: 1.6116x; 1.0345x over previous
#include <cuda_runtime.h>
#include <cuda_bf16.h>
#include <math.h>
#include <stdint.h>

#define QN 4
#define DD 768
#define NN 1024
#define HH 512
#define MM 8192
#define DD2 1536

// ---------------- device scratch (no runtime allocation) -------------------
__device__ float g_res[MM*DD];
__device__ __align__(128) __nv_bfloat16 g_Ahi[MM*DD];
__device__ __align__(128) __nv_bfloat16 g_Alo[MM*DD];
__device__ __align__(128) __nv_bfloat16 g_Hhi[MM*DD2];
__device__ __align__(128) __nv_bfloat16 g_Hlo[MM*DD2];
#define WT_TOTAL 6029312
__device__ __align__(128) __nv_bfloat16 g_Wthi[WT_TOTAL];
__device__ __align__(128) __nv_bfloat16 g_Wtlo[WT_TOTAL];

// weight-split layout (elements)
#define O_P1 0
#define SZ_P1 393216            /* 512*768  */
#define O_P2 1572864
#define SZ_P2 524288            /* 1024*512 */
#define O_D1 3670016
#define O_D2 4849664

// ---------------- PTX helpers ----------------------------------------------
__device__ __forceinline__ uint32_t smem_u32(const void* p) {
    uint32_t a;
    asm("{ .reg .u64 t; cvta.to.shared.u64 t, %1; cvt.u32.u64 %0, t; }" : "=r"(a) : "l"(p));
    return a;
}
#define CP_ASYNC16(dst, src) \
    asm volatile("cp.async.cg.shared.global [%0], [%1], 16;\n" :: "r"(dst), "l"(src))
#define CP_COMMIT() asm volatile("cp.async.commit_group;\n" ::: "memory")
#define CP_WAIT(n)  asm volatile("cp.async.wait_group %0;\n" :: "n"(n) : "memory")

#define LDSM4(f, addr) \
    asm volatile("ldmatrix.sync.aligned.m8n8.x4.shared.b16 {%0,%1,%2,%3}, [%4];\n" \
        : "=r"((f)[0]), "=r"((f)[1]), "=r"((f)[2]), "=r"((f)[3]) : "r"(addr))

#define MMA16816(d, a, b0, b1) \
    asm volatile("mma.sync.aligned.m16n8k16.row.col.f32.bf16.bf16.f32 " \
        "{%0,%1,%2,%3}, {%4,%5,%6,%7}, {%8,%9}, {%0,%1,%2,%3};\n" \
        : "+f"((d)[0]), "+f"((d)[1]), "+f"((d)[2]), "+f"((d)[3]) \
        : "r"((a)[0]), "r"((a)[1]), "r"((a)[2]), "r"((a)[3]), "r"(b0), "r"(b1))

// ---------------- small kernels --------------------------------------------
// init: res=x, split(x) -> Ahi/Alo
__global__ void init_kernel(const float* __restrict__ x) {
    int i = blockIdx.x * blockDim.x + threadIdx.x;
    if (i >= MM*DD/4) return;
    float4 a = ((const float4*)x)[i];
    ((float4*)g_res)[i] = a;
    float av[4] = {a.x, a.y, a.z, a.w};
    __nv_bfloat16 h[4], l[4];
#pragma unroll
    for (int j = 0; j < 4; j++) {
        h[j] = __float2bfloat16(av[j]);
        l[j] = __float2bfloat16(av[j] - __bfloat162float(h[j]));
    }
    ((ushort4*)g_Ahi)[i] = make_ushort4(*(unsigned short*)&h[0], *(unsigned short*)&h[1],
                                        *(unsigned short*)&h[2], *(unsigned short*)&h[3]);
    ((ushort4*)g_Alo)[i] = make_ushort4(*(unsigned short*)&l[0], *(unsigned short*)&l[1],
                                        *(unsigned short*)&l[2], *(unsigned short*)&l[3]);
}

// ALL weight transposes+splits in ONE launch.
// Tile map (32x32 tiles): [0,1536) pW1 x4 (384 each); [1536,3584) pW2 x4 (512 each);
// [3584,4736) dW1 (1152); [4736,5888) dW2 (1152).
__global__ void wsplit_all(const float* __restrict__ pW1, const float* __restrict__ pW2,
                           const float* __restrict__ dW1, const float* __restrict__ dW2) {
    __shared__ float t[32][33];
    int tb = blockIdx.x;
    const float* W;
    int K, N;
    size_t dstoff;
    if (tb < 1536) {
        int i = tb / 384; tb -= i * 384;
        W = pW1 + (size_t)i * DD * HH; K = DD; N = HH; dstoff = O_P1 + (size_t)i * SZ_P1;
    } else if (tb < 3584) {
        int u = tb - 1536; int i = u / 512; tb = u - i * 512;
        W = pW2 + (size_t)i * HH * NN; K = HH; N = NN; dstoff = O_P2 + (size_t)i * SZ_P2;
    } else if (tb < 4736) {
        tb -= 3584; W = dW1; K = DD; N = DD2; dstoff = O_D1;
    } else {
        tb -= 4736; W = dW2; K = DD2; N = DD; dstoff = O_D2;
    }
    int ntx = N >> 5;
    int n0 = (tb % ntx) << 5, k0 = (tb / ntx) << 5;
    __nv_bfloat16* Thi = g_Wthi + dstoff;
    __nv_bfloat16* Tlo = g_Wtlo + dstoff;
    for (int i = threadIdx.y; i < 32; i += 8)
        t[i][threadIdx.x] = W[(size_t)(k0 + i) * N + n0 + threadIdx.x];
    __syncthreads();
    for (int i = threadIdx.y; i < 32; i += 8) {
        float val = t[threadIdx.x][i];
        __nv_bfloat16 h = __float2bfloat16(val);
        size_t o = (size_t)(n0 + i) * K + k0 + threadIdx.x;
        Thi[o] = h;
        Tlo[o] = __float2bfloat16(val - __bfloat162float(h));
    }
}

// ---------------- mma.sync split-bf16 GEMM (unchanged from R7) --------------
#define GS_STAGE 65536            /* 32KB A(hi|lo) + 32KB W(hi|lo) */
#define GS_SC    196608
#define SMEM_G   (196608 + 1024)

__global__ __launch_bounds__(256, 1)
void mma_gemm(const __nv_bfloat16* __restrict__ Ahi, const __nv_bfloat16* __restrict__ Alo,
              const __nv_bfloat16* __restrict__ Whi, const __nv_bfloat16* __restrict__ Wlo,
              const float* __restrict__ bb, const float* __restrict__ gg,
              const float* __restrict__ be, const float* __restrict__ mm_,
              const float* __restrict__ vv,
              float* __restrict__ Cf, __nv_bfloat16* __restrict__ Chi,
              __nv_bfloat16* __restrict__ Clo, int K, int mode)
{
    extern __shared__ __align__(1024) char smem[];
    const uint32_t sbase = smem_u32(smem);
    float* scp = (float*)(smem + GS_SC);
    float* ofp = scp + 128;
    const int tid = threadIdx.x;
    const int Nc = gridDim.x * 128;
    const int n0 = blockIdx.x * 128;
    const int m0 = blockIdx.y * 128;

    if (tid < 128) {
        int c = n0 + tid;
        float s = gg[c] * rsqrtf(vv[c] + 1e-5f);
        scp[tid] = s;
        ofp[tid] = (bb[c] - mm_[c]) * s + be[c];
    }

    const int lane = tid & 31, wid = tid >> 5;
    const int wm = (wid >> 2) << 6;
    const int wn = (wid & 3) << 5;

    float acc[4][4][4];
#pragma unroll
    for (int im = 0; im < 4; im++)
#pragma unroll
        for (int in = 0; in < 4; in++)
#pragma unroll
            for (int r = 0; r < 4; r++) acc[im][in][r] = 0.f;

    uint32_t aoff[4]; int asw[4];
#pragma unroll
    for (int im = 0; im < 4; im++) {
        int r = wm + (im << 4) + (lane & 15);
        aoff[im] = (uint32_t)(r << 8);
        asw[im] = r & 7;
    }
    const int acb = lane >> 4;
    uint32_t boff[2]; int bsw[2];
#pragma unroll
    for (int jn = 0; jn < 2; jn++) {
        int r = wn + (jn << 4) + (lane & 7) + (((lane >> 4) & 1) << 3);
        boff[jn] = (uint32_t)(r << 8);
        bsw[jn] = r & 7;
    }
    const int bcb = (lane >> 3) & 1;

    const int NC = K >> 6;

    const int lrow0 = tid >> 4;
    const int lc16  = tid & 15;
    const int lhalf = lc16 >> 3;
    const int lcc   = lc16 & 7;
    const __nv_bfloat16* Asrc = lhalf ? Alo : Ahi;
    const __nv_bfloat16* Wsrc = lhalf ? Wlo : Whi;
    const uint32_t lhoff = (uint32_t)(lhalf << 7);

    auto load_chunk = [&](int c, int s) {
        int k0 = c << 6;
        uint32_t bA = sbase + s * GS_STAGE;
        uint32_t bB = bA + 32768;
#pragma unroll
        for (int j = 0; j < 8; j++) {
            int row = lrow0 + (j << 4);
            uint32_t sw = (uint32_t)(row << 8) + lhoff + (uint32_t)((lcc ^ (row & 7)) << 4);
            CP_ASYNC16(bA + sw, Asrc + (size_t)(m0 + row) * K + k0 + (lcc << 3));
            CP_ASYNC16(bB + sw, Wsrc + (size_t)(n0 + row) * K + k0 + (lcc << 3));
        }
    };

    load_chunk(0, 0); CP_COMMIT();
    load_chunk(1, 1); CP_COMMIT();

    for (int c = 0; c < NC; c++) {
        CP_WAIT(1);
        __syncthreads();
        if (c + 2 < NC) load_chunk(c + 2, (c + 2) % 3);
        CP_COMMIT();

        uint32_t sA = sbase + (c % 3) * GS_STAGE;
        uint32_t sB = sA + 32768;
#pragma unroll
        for (int kk = 0; kk < 4; kk++) {
            uint32_t afh[4][4], afl[4][4], bfh[2][4], bfl[2][4];
            const int sela = (kk << 1) + acb;
            const int selb = (kk << 1) + bcb;
#pragma unroll
            for (int im = 0; im < 4; im++) {
                uint32_t base = sA + aoff[im] + (uint32_t)((sela ^ asw[im]) << 4);
                LDSM4(afh[im], base);
                LDSM4(afl[im], base + 128);
            }
#pragma unroll
            for (int jn = 0; jn < 2; jn++) {
                uint32_t base = sB + boff[jn] + (uint32_t)((selb ^ bsw[jn]) << 4);
                LDSM4(bfh[jn], base);
                LDSM4(bfl[jn], base + 128);
            }
#pragma unroll
            for (int im = 0; im < 4; im++)
#pragma unroll
                for (int in = 0; in < 4; in++) {
                    const uint32_t* bp = bfh[in >> 1];
                    if (in & 1) MMA16816(acc[im][in], afh[im], bp[2], bp[3]);
                    else        MMA16816(acc[im][in], afh[im], bp[0], bp[1]);
                }
#pragma unroll
            for (int im = 0; im < 4; im++)
#pragma unroll
                for (int in = 0; in < 4; in++) {
                    const uint32_t* bp = bfl[in >> 1];
                    if (in & 1) MMA16816(acc[im][in], afh[im], bp[2], bp[3]);
                    else        MMA16816(acc[im][in], afh[im], bp[0], bp[1]);
                }
#pragma unroll
            for (int im = 0; im < 4; im++)
#pragma unroll
                for (int in = 0; in < 4; in++) {
                    const uint32_t* bp = bfh[in >> 1];
                    if (in & 1) MMA16816(acc[im][in], afl[im], bp[2], bp[3]);
                    else        MMA16816(acc[im][in], afl[im], bp[0], bp[1]);
                }
        }
    }

    const int rbase = m0 + wm + (lane >> 2);
    const int clbase = wn + ((lane & 3) << 1);
#pragma unroll
    for (int im = 0; im < 4; im++) {
#pragma unroll
        for (int in = 0; in < 4; in++) {
            int row = rbase + (im << 4);
            int cl = clbase + (in << 3);
            float s0 = scp[cl], s1 = scp[cl + 1];
            float o0 = ofp[cl], o1 = ofp[cl + 1];
            float v0 = fmaxf(acc[im][in][0] * s0 + o0, 0.f);
            float v1 = fmaxf(acc[im][in][1] * s1 + o1, 0.f);
            float v2 = fmaxf(acc[im][in][2] * s0 + o0, 0.f);
            float v3 = fmaxf(acc[im][in][3] * s1 + o1, 0.f);
            size_t p0 = (size_t)row * Nc + n0 + cl;
            size_t p1 = (size_t)(row + 8) * Nc + n0 + cl;
            if (mode == 0) {
                float2 w0; w0.x = v0; w0.y = v1;
                float2 w1; w1.x = v2; w1.y = v3;
                *(float2*)&Cf[p0] = w0;
                *(float2*)&Cf[p1] = w1;
            } else {
                __nv_bfloat16 h0 = __float2bfloat16(v0);
                __nv_bfloat16 h1 = __float2bfloat16(v1);
                __nv_bfloat16 h2 = __float2bfloat16(v2);
                __nv_bfloat16 h3 = __float2bfloat16(v3);
                __nv_bfloat162 hp0; hp0.x = h0; hp0.y = h1;
                __nv_bfloat162 hp1; hp1.x = h2; hp1.y = h3;
                __nv_bfloat162 lp0, lp1;
                lp0.x = __float2bfloat16(v0 - __bfloat162float(h0));
                lp0.y = __float2bfloat16(v1 - __bfloat162float(h1));
                lp1.x = __float2bfloat16(v2 - __bfloat162float(h2));
                lp1.y = __float2bfloat16(v3 - __bfloat162float(h3));
                *(__nv_bfloat162*)&Chi[p0] = hp0;
                *(__nv_bfloat162*)&Chi[p1] = hp1;
                *(__nv_bfloat162*)&Clo[p0] = lp0;
                *(__nv_bfloat162*)&Clo[p1] = lp1;
            }
        }
    }
}

// ---------------- token kernel (float4 everywhere) ---------------------------
// Each thread owns 4 contiguous logits (one float4). 256 threads * 4 = 1024.
// split_mode 0: res -= cb[idx]; emit split(res). 1: emit split(x - (res-cb)).
__global__ void token_kernel(const float* __restrict__ z,
                             const float* __restrict__ gum,
                             const float* __restrict__ cb,
                             const float* __restrict__ x,
                             float* __restrict__ ent_out,
                             float* __restrict__ lat_out,
                             float* __restrict__ idx_out,
                             int split_mode)
{
    const int t = blockIdx.x;
    const int tid = threadIdx.x;
    const int lane = tid & 31, wrp = tid >> 5;

    __shared__ float swa[8];
    __shared__ float swb[8];
    __shared__ int   swi[8];

    float4 z4 = ((const float4*)(z + (size_t)t * NN))[tid];
    float4 g4 = ((const float4*)(gum + (size_t)t * NN))[tid];
    float zv[4] = {z4.x, z4.y, z4.z, z4.w};
    float gv[4] = {g4.x, g4.y, g4.z, g4.w};

    float lmax = -INFINITY;
    float amax = -INFINITY;
    int   aidx = 0x7fffffff;
#pragma unroll
    for (int k = 0; k < 4; k++) {
        lmax = fmaxf(lmax, zv[k]);
        float lg = zv[k] + gv[k];
        if (lg > amax) { amax = lg; aidx = (tid << 2) + k; }
    }
#pragma unroll
    for (int o = 16; o > 0; o >>= 1) {
        lmax = fmaxf(lmax, __shfl_xor_sync(0xffffffffu, lmax, o));
        float ov = __shfl_xor_sync(0xffffffffu, amax, o);
        int   oi = __shfl_xor_sync(0xffffffffu, aidx, o);
        if (ov > amax || (ov == amax && oi < aidx)) { amax = ov; aidx = oi; }
    }
    if (lane == 0) { swa[wrp] = lmax; swb[wrp] = amax; swi[wrp] = aidx; }
    __syncthreads();
    float zmax = swa[0];
    float bv = swb[0]; int bi = swi[0];
#pragma unroll
    for (int w = 1; w < 8; w++) {
        zmax = fmaxf(zmax, swa[w]);
        float ov = swb[w]; int oi = swi[w];
        if (ov > bv || (ov == bv && oi < bi)) { bv = ov; bi = oi; }
    }
    const int idx = bi;
    __syncthreads();

    float ex[4];
    float se = 0.f;
#pragma unroll
    for (int k = 0; k < 4; k++) { ex[k] = expf(zv[k] - zmax); se += ex[k]; }
#pragma unroll
    for (int o = 16; o > 0; o >>= 1) se += __shfl_xor_sync(0xffffffffu, se, o);
    if (lane == 0) swa[wrp] = se;
    __syncthreads();
    float tot = 0.f;
#pragma unroll
    for (int w = 0; w < 8; w++) tot += swa[w];
    const float inv = 1.f / tot;

    float entp = 0.f;
    float lt[4];
#pragma unroll
    for (int k = 0; k < 4; k++) {
        float qy = ex[k] * inv;
        entp -= qy * logf(qy + 1e-10f);
        lt[k] = qy * logf(qy * 1024.f + 1e-10f);
    }
    float4 l4; l4.x = lt[0]; l4.y = lt[1]; l4.z = lt[2]; l4.w = lt[3];
    ((float4*)(lat_out + (size_t)t * NN))[tid] = l4;
#pragma unroll
    for (int o = 16; o > 0; o >>= 1) entp += __shfl_xor_sync(0xffffffffu, entp, o);
    __syncthreads();
    if (lane == 0) swb[wrp] = entp;
    __syncthreads();
    if (tid == 0) {
        float e = 0.f;
#pragma unroll
        for (int w = 0; w < 8; w++) e += swb[w];
        ent_out[t] = e;
        idx_out[t] = (float)idx;
    }

    // codebook gather + residual update, float4 (DD/4 = 192 quads)
    if (tid < DD/4) {
        const float4* cb4 = (const float4*)(cb + (size_t)idx * DD);
        float4* rr4 = (float4*)(g_res + (size_t)t * DD);
        float4 c4 = cb4[tid];
        float4 r4 = rr4[tid];
        r4.x -= c4.x; r4.y -= c4.y; r4.z -= c4.z; r4.w -= c4.w;
        float sv[4];
        if (split_mode) {
            float4 x4 = ((const float4*)(x + (size_t)t * DD))[tid];
            sv[0] = x4.x - r4.x; sv[1] = x4.y - r4.y;
            sv[2] = x4.z - r4.z; sv[3] = x4.w - r4.w;
        } else {
            rr4[tid] = r4;
            sv[0] = r4.x; sv[1] = r4.y; sv[2] = r4.z; sv[3] = r4.w;
        }
        __nv_bfloat16 h[4], l[4];
#pragma unroll
        for (int k = 0; k < 4; k++) {
            h[k] = __float2bfloat16(sv[k]);
            l[k] = __float2bfloat16(sv[k] - __bfloat162float(h[k]));
        }
        ((ushort4*)(g_Ahi + (size_t)t * DD))[tid] =
            make_ushort4(*(unsigned short*)&h[0], *(unsigned short*)&h[1],
                         *(unsigned short*)&h[2], *(unsigned short*)&h[3]);
        ((ushort4*)(g_Alo + (size_t)t * DD))[tid] =
            make_ushort4(*(unsigned short*)&l[0], *(unsigned short*)&l[1],
                         *(unsigned short*)&l[2], *(unsigned short*)&l[3]);
    }
}

// ---------------- host launch ----------------------------------------------
extern "C" void kernel_launch(void* const* d_in, const int* in_sizes, int n_in,
                              void* d_out, int out_size)
{
    const float* x    = (const float*)d_in[0];
    const float* cb   = (const float*)d_in[1];
    const float* pW1  = (const float*)d_in[2];
    const float* pb1  = (const float*)d_in[3];
    const float* pg1  = (const float*)d_in[4];
    const float* pbe1 = (const float*)d_in[5];
    const float* pm1  = (const float*)d_in[6];
    const float* pv1  = (const float*)d_in[7];
    const float* pW2  = (const float*)d_in[8];
    const float* pb2  = (const float*)d_in[9];
    const float* pg2  = (const float*)d_in[10];
    const float* pbe2 = (const float*)d_in[11];
    const float* pm2  = (const float*)d_in[12];
    const float* pv2  = (const float*)d_in[13];
    const float* dW1  = (const float*)d_in[14];
    const float* db1  = (const float*)d_in[15];
    const float* dg1  = (const float*)d_in[16];
    const float* dbe1 = (const float*)d_in[17];
    const float* dm1  = (const float*)d_in[18];
    const float* dv1  = (const float*)d_in[19];
    const float* dW2  = (const float*)d_in[20];
    const float* db2  = (const float*)d_in[21];
    const float* dg2  = (const float*)d_in[22];
    const float* dbe2 = (const float*)d_in[23];
    const float* dm2  = (const float*)d_in[24];
    const float* dv2  = (const float*)d_in[25];
    const float* gum  = (const float*)d_in[26];

    float* out  = (float*)d_out;
    float* xhat = out;                                  // [MM, DD]
    float* ent  = xhat + (size_t)MM * DD;               // [QN, MM]
    float* lat  = ent  + (size_t)QN * MM;               // [QN, MM, NN]
    float* idxo = lat  + (size_t)QN * MM * NN;          // [QN, MM]
    float* zs   = idxo + (size_t)QN * MM;               // [QN, MM, NN]

    __nv_bfloat16 *Ahi, *Alo, *Hhi, *Hlo, *Wthi, *Wtlo;
    cudaGetSymbolAddress((void**)&Ahi,  g_Ahi);
    cudaGetSymbolAddress((void**)&Alo,  g_Alo);
    cudaGetSymbolAddress((void**)&Hhi,  g_Hhi);
    cudaGetSymbolAddress((void**)&Hlo,  g_Hlo);
    cudaGetSymbolAddress((void**)&Wthi, g_Wthi);
    cudaGetSymbolAddress((void**)&Wtlo, g_Wtlo);

    cudaFuncSetAttribute(mma_gemm, cudaFuncAttributeMaxDynamicSharedMemorySize, SMEM_G);

    init_kernel<<<(MM*DD/4 + 255) / 256, 256>>>(x);
    wsplit_all<<<5888, dim3(32, 8)>>>(pW1, pW2, dW1, dW2);

    for (int i = 0; i < QN; i++) {
        // h = blk(res @ pW1) -> bf16 split [8192 x 512]
        mma_gemm<<<dim3(HH/128, MM/128), 256, SMEM_G>>>(
            Ahi, Alo, Wthi + O_P1 + (size_t)i*SZ_P1, Wtlo + O_P1 + (size_t)i*SZ_P1,
            pb1 + i*HH, pg1 + i*HH, pbe1 + i*HH, pm1 + i*HH, pv1 + i*HH,
            nullptr, Hhi, Hlo, DD, 1);
        // z = blk(h @ pW2) -> fp32 zs slice [8192 x 1024]
        float* z_i = zs + (size_t)i * MM * NN;
        mma_gemm<<<dim3(NN/128, MM/128), 256, SMEM_G>>>(
            Hhi, Hlo, Wthi + O_P2 + (size_t)i*SZ_P2, Wtlo + O_P2 + (size_t)i*SZ_P2,
            pb2 + i*NN, pg2 + i*NN, pbe2 + i*NN, pm2 + i*NN, pv2 + i*NN,
            z_i, nullptr, nullptr, HH, 0);
        token_kernel<<<MM, 256>>>(
            z_i, gum + (size_t)i * MM * NN, cb + (size_t)i * NN * DD, x,
            ent + (size_t)i * MM, lat + (size_t)i * MM * NN, idxo + (size_t)i * MM,
            (i == QN - 1) ? 1 : 0);
    }

    // decoder (Ahi/Alo hold split(qout))
    mma_gemm<<<dim3(DD2/128, MM/128), 256, SMEM_G>>>(
        Ahi, Alo, Wthi + O_D1, Wtlo + O_D1,
        db1, dg1, dbe1, dm1, dv1,
        nullptr, Hhi, Hlo, DD, 1);
    mma_gemm<<<dim3(DD/128, MM/128), 256, SMEM_G>>>(
        Hhi, Hlo, Wthi + O_D2, Wtlo + O_D2,
        db2, dg2, dbe2, dm2, dv2,
        xhat, nullptr, nullptr, DD2, 0);
}